// round 14
// baseline (speedup 1.0000x reference)
#include <cuda_runtime.h>

// RNN_33964601377372: h_{t+1} = relu(x_t*W_ih + b_ih + b_hh + W_hh h_t), out = fc(h_T)
//
// R13 skeleton (scalar FFMA, L=8 row-split, no per-step sync, 2 warps/SMSP)
// with a shortened critical path: each row's 20-term dot product runs as TWO
// independent 10-deep FFMA chains combined by one FADD (chain 80 -> 44 cyc),
// and the h-gather LDS.128s issue at the top of the step so their latency
// overlaps the independent x-proj seeds. block=256, grid=128.

#define HID 20

__device__ __forceinline__ void lds_v4f32(unsigned addr, float& a, float& b,
                                          float& c, float& d) {
    asm volatile("ld.shared.v4.f32 {%0, %1, %2, %3}, [%4];"
                 : "=f"(a), "=f"(b), "=f"(c), "=f"(d) : "r"(addr));
}
__device__ __forceinline__ void sts_f32(unsigned addr, float v) {
    asm volatile("st.shared.f32 [%0], %1;" :: "r"(addr), "f"(v));
}
__device__ __forceinline__ float lds_f32(unsigned addr) {
    float v; asm volatile("ld.shared.f32 %0, [%1];" : "=f"(v) : "r"(addr)); return v;
}

#define ROW_PAD 24   // floats per h row (96B): conflict-free 16B reads & stores

__global__ __launch_bounds__(256) void rnn_fused_kernel(
    const float* __restrict__ x,    // [B, T]
    const float* __restrict__ Wih,  // [H]
    const float* __restrict__ Whh,  // [H, H] row-major
    const float* __restrict__ bih,  // [H]
    const float* __restrict__ bhh,  // [H]
    const float* __restrict__ fcw,  // [H]
    const float* __restrict__ fcb,  // [1]
    float* __restrict__ out,        // [B]
    int B, int T)
{
    __shared__ float hbuf[32][ROW_PAD];

    const int lt = threadIdx.x;
    const int g  = lt >> 3;            // batch within CTA (0..31)
    const int e  = lt & 7;             // lane within batch group
    int batch = blockIdx.x * 32 + g;
    const bool real = (batch < B);
    if (!real) batch = B - 1;          // clamp; lane stays resident

    // Owned rows; lanes e>=4 duplicate row e as third (same value, same addr).
    const int r_[3] = { e, 8 + e, (e < 4) ? 16 + e : e };

    // Scalar weights for my 3 rows.
    float wS[3][HID];
#pragma unroll
    for (int r = 0; r < 3; ++r)
#pragma unroll
        for (int j = 0; j < HID; ++j)
            wS[r][j] = Whh[r_[r] * HID + j];

    float wih[3], bias[3];
#pragma unroll
    for (int r = 0; r < 3; ++r) {
        wih[r]  = Wih[r_[r]];
        bias[r] = bih[r_[r]] + bhh[r_[r]];
    }

    const unsigned sbase =
        (unsigned)__cvta_generic_to_shared(&hbuf[g][0]);   // 96B stride

    // h(0) = 0; later same-warp LDS observe it in program order.
#pragma unroll
    for (int r = 0; r < 3; ++r) sts_f32(sbase + 4u * r_[r], 0.0f);

    const float* xb = x + (size_t)batch * T;    // 4000B stride, 16B-aligned
    const float4* xb4 = (const float4*)xb;
    const int nChunks = T >> 2;                 // 250 for T=1000

    auto step = [&](float xt) {
        // Gather h_t FIRST: 5 vector loads; latency overlaps the seeds below.
        float h[HID];
#pragma unroll
        for (int i = 0; i < 5; ++i)
            lds_v4f32(sbase + 16u * i,
                      h[4 * i], h[4 * i + 1], h[4 * i + 2], h[4 * i + 3]);

        // Independent seeds while the LDS are in flight.
        float accA[3], accB[3];
#pragma unroll
        for (int r = 0; r < 3; ++r)
            accA[r] = fmaf(xt, wih[r], bias[r]);

        // Two 10-deep chains per row (6 independent chains total).
#pragma unroll
        for (int r = 0; r < 3; ++r)
            accB[r] = h[10] * wS[r][10];
#pragma unroll
        for (int j = 0; j < 10; ++j)
#pragma unroll
            for (int r = 0; r < 3; ++r)
                accA[r] = fmaf(h[j], wS[r][j], accA[r]);
#pragma unroll
        for (int j = 11; j < HID; ++j)
#pragma unroll
            for (int r = 0; r < 3; ++r)
                accB[r] = fmaf(h[j], wS[r][j], accB[r]);

#pragma unroll
        for (int r = 0; r < 3; ++r)
            sts_f32(sbase + 4u * r_[r], fmaxf(accA[r] + accB[r], 0.0f));
    };

    // Deep x prefetch: 2 chunks (8 steps) in flight.
    float4 x0 = make_float4(0.f, 0.f, 0.f, 0.f);
    float4 x1 = x0;
    if (nChunks > 0) x0 = xb4[0];
    if (nChunks > 1) x1 = xb4[1];

    for (int c = 0; c < nChunks; ++c) {
        float4 x2 = x1;
        if (c + 2 < nChunks) x2 = xb4[c + 2];
        step(x0.x);
        step(x0.y);
        step(x0.z);
        step(x0.w);
        x0 = x1;
        x1 = x2;
    }
    for (int t = nChunks << 2; t < T; ++t) step(xb[t]);  // tail (unused @T=1000)

    __syncwarp();   // one-time: publish final h for head reads

    // Head: out[b] = h . fc_w + fc_b over owned rows (dummy masked), then
    // xor-reduce across the 8-lane group.
    float p = lds_f32(sbase + 4u * r_[0]) * fcw[r_[0]]
            + lds_f32(sbase + 4u * r_[1]) * fcw[r_[1]];
    if (e < 4) p += lds_f32(sbase + 4u * r_[2]) * fcw[r_[2]];
    p += __shfl_xor_sync(0xffffffffu, p, 1, 8);
    p += __shfl_xor_sync(0xffffffffu, p, 2, 8);
    p += __shfl_xor_sync(0xffffffffu, p, 4, 8);
    if (e == 0 && real) out[batch] = p + fcb[0];
}

extern "C" void kernel_launch(void* const* d_in, const int* in_sizes, int n_in,
                              void* d_out, int out_size)
{
    const float* x    = (const float*)d_in[0];
    const float* Wih  = (const float*)d_in[1];
    const float* Whh  = (const float*)d_in[2];
    const float* bih  = (const float*)d_in[3];
    const float* bhh  = (const float*)d_in[4];
    const float* fcw  = (const float*)d_in[5];
    const float* fcb  = (const float*)d_in[6];
    float* out = (float*)d_out;

    int B = out_size;
    int T = in_sizes[0] / B;

    const int threads = 256;            // 8 warps -> 2 per SMSP; 32 batches/CTA
    int blocks = (B + 31) / 32;         // 128 CTAs at B=4096
    rnn_fused_kernel<<<blocks, threads>>>(x, Wih, Whh, bih, bhh, fcw, fcb, out, B, T);
}

// round 15
// speedup vs baseline: 1.2665x; 1.2665x over previous
#include <cuda_runtime.h>

// RNN_33964601377372: h_{t+1} = relu(x_t*W_ih + b_ih + b_hh + W_hh h_t), out = fc(h_T)
//
// R1 body (scalar FFMA quad layout — the proven 99us champion, measured to be
// EXACTLY 2-warps-per-SMSP issue-bound at 2x107 cyc/step) relaunched at
// block=128 / grid=128: one warp per SMSP. Session model: scalar FFMA rt=1,
// shuffle exchange runs at 100% issue efficiency; at 1 warp/SMSP the wall
// drops from 2x slots (214) toward max(slots ~107, crit path ~115-130).
// Per lane: 5 rows, 20 width-4 shuffles, 105 scalar FFMA (lat 4, 5 indep
// chains), 5 FMNMX. x prefetched 2 float4 chunks (8 steps) ahead.

#define HID 20
#define QUAD 4

__global__ __launch_bounds__(128) void rnn_fused_kernel(
    const float* __restrict__ x,    // [B, T]
    const float* __restrict__ Wih,  // [H]
    const float* __restrict__ Whh,  // [H, H] row-major
    const float* __restrict__ bih,  // [H]
    const float* __restrict__ bhh,  // [H]
    const float* __restrict__ fcw,  // [H]
    const float* __restrict__ fcb,  // [1]
    float* __restrict__ out,        // [B]
    int B, int T)
{
    int tid = blockIdx.x * blockDim.x + threadIdx.x;
    int batch = tid >> 2;
    int q = tid & 3;                  // lane within quad: rows q*5 .. q*5+4
    if (batch >= B) return;
    const int r0 = q * 5;

    // Per-lane weight slice in registers (fully unrolled -> no local memory).
    float w[5][HID];
#pragma unroll
    for (int r = 0; r < 5; ++r)
#pragma unroll
        for (int j = 0; j < HID; ++j)
            w[r][j] = Whh[(r0 + r) * HID + j];

    float wih[5], bias[5], h[5];
#pragma unroll
    for (int r = 0; r < 5; ++r) {
        wih[r]  = Wih[r0 + r];
        bias[r] = bih[r0 + r] + bhh[r0 + r];
        h[r]    = 0.0f;
    }

    const float* xb = x + (size_t)batch * T;   // 4000B row stride, 16B-aligned
    const float4* xb4 = (const float4*)xb;
    const int nChunks = T >> 2;

    // Deep prefetch: 2 chunks (8 steps) in flight.
    float4 x0 = make_float4(0.f, 0.f, 0.f, 0.f);
    float4 x1 = x0;
    if (nChunks > 0) x0 = xb4[0];
    if (nChunks > 1) x1 = xb4[1];

    auto step = [&](float xt) {
        float acc[5];
#pragma unroll
        for (int r = 0; r < 5; ++r) acc[r] = fmaf(xt, wih[r], bias[r]);
#pragma unroll
        for (int j = 0; j < HID; ++j) {
            // h_j lives in register (j%5) of quad-lane (j/5); consts after unroll.
            float hj = __shfl_sync(0xffffffffu, h[j % 5], j / 5, QUAD);
#pragma unroll
            for (int r = 0; r < 5; ++r) acc[r] = fmaf(hj, w[r][j], acc[r]);
        }
#pragma unroll
        for (int r = 0; r < 5; ++r) h[r] = fmaxf(acc[r], 0.0f);
    };

    for (int c = 0; c < nChunks; ++c) {
        float4 x2 = x1;
        if (c + 2 < nChunks) x2 = xb4[c + 2];
        step(x0.x);
        step(x0.y);
        step(x0.z);
        step(x0.w);
        x0 = x1;
        x1 = x2;
    }
    for (int t = nChunks << 2; t < T; ++t) step(xb[t]);  // tail (unused @T=1000)

    // Head: out[b] = h . fc_w + fc_b ; quad butterfly reduction.
    float p = 0.0f;
#pragma unroll
    for (int r = 0; r < 5; ++r) p = fmaf(h[r], fcw[r0 + r], p);
    p += __shfl_xor_sync(0xffffffffu, p, 1, QUAD);
    p += __shfl_xor_sync(0xffffffffu, p, 2, QUAD);
    if (q == 0) out[batch] = p + fcb[0];
}

extern "C" void kernel_launch(void* const* d_in, const int* in_sizes, int n_in,
                              void* d_out, int out_size)
{
    const float* x    = (const float*)d_in[0];
    const float* Wih  = (const float*)d_in[1];
    const float* Whh  = (const float*)d_in[2];
    const float* bih  = (const float*)d_in[3];
    const float* bhh  = (const float*)d_in[4];
    const float* fcw  = (const float*)d_in[5];
    const float* fcb  = (const float*)d_in[6];
    float* out = (float*)d_out;

    int B = out_size;
    int T = in_sizes[0] / B;

    const int threads = 128;             // 4 warps -> ONE per SMSP; 32 batches/CTA
    int total = B * QUAD;                // 16384 lanes
    int blocks = (total + threads - 1) / threads;   // 128 CTAs at B=4096
    rnn_fused_kernel<<<blocks, threads>>>(x, Wih, Whh, bih, bhh, fcw, fcb, out, B, T);
}